// round 12
// baseline (speedup 1.0000x reference)
#include <cuda_runtime.h>
#include <cuda_fp16.h>
#include <cstdint>
#include <math.h>

// ---------------- Problem constants ----------------
#define T_TOK   1024
#define HDIM    1024
#define NEXP    64
#define TOPK    6
#define NGRP    8
#define TOPG    4
#define FDIM    512
#define FSH     1024
#define CAP     384
#define SCALE   2.5f
#define KSPLIT  8
#define KSEG    (HDIM / KSPLIT)   // 128

// ---------------- Device scratch ----------------
__device__ __align__(16) __half g_buf16 [(size_t)NEXP * CAP * HDIM];
__device__ __align__(16) __half g_act16 [(size_t)NEXP * CAP * FDIM];
__device__ __align__(16) __half g_eo16  [(size_t)NEXP * CAP * HDIM];
__device__ __align__(16) __half g_x16   [(size_t)T_TOK * HDIM];
__device__ __align__(16) __half g_acts16[(size_t)T_TOK * FSH];
__device__ __align__(16) float  g_logP  [(size_t)KSPLIT * T_TOK * NEXP];
__device__ int   g_cnt[NEXP];
__device__ int   g_ids[T_TOK * TOPK];
__device__ int   g_pos[T_TOK * TOPK];
__device__ float g_wts[T_TOK * TOPK];

// ---------------- PTX helpers ----------------
static __device__ __forceinline__ uint32_t s2u(const void* p) {
    uint32_t a;
    asm("{ .reg .u64 t; cvta.to.shared.u64 t, %1; cvt.u32.u64 %0, t; }" : "=r"(a) : "l"(p));
    return a;
}
#define CPA16(dst, src) asm volatile("cp.async.cg.shared.global [%0], [%1], 16;" :: "r"(dst), "l"(src))
#define CP_COMMIT()     asm volatile("cp.async.commit_group;")
#define CP_WAIT0()      asm volatile("cp.async.wait_group 0;")
#define LDSM4(r, addr) \
    asm volatile("ldmatrix.sync.aligned.m8n8.x4.shared.b16 {%0,%1,%2,%3}, [%4];" \
        : "=r"((r)[0]), "=r"((r)[1]), "=r"((r)[2]), "=r"((r)[3]) : "r"(addr))
#define LDSM4T(r, addr) \
    asm volatile("ldmatrix.sync.aligned.m8n8.x4.trans.shared.b16 {%0,%1,%2,%3}, [%4];" \
        : "=r"((r)[0]), "=r"((r)[1]), "=r"((r)[2]), "=r"((r)[3]) : "r"(addr))
#define MMA16816(d, a, b0, b1) \
    asm volatile("mma.sync.aligned.m16n8k16.row.col.f32.f16.f16.f32 " \
        "{%0,%1,%2,%3}, {%4,%5,%6,%7}, {%8,%9}, {%0,%1,%2,%3};" \
        : "+f"((d)[0]), "+f"((d)[1]), "+f"((d)[2]), "+f"((d)[3]) \
        : "r"((a)[0]), "r"((a)[1]), "r"((a)[2]), "r"((a)[3]), "r"(b0), "r"(b1))

// SMEM tile geometry (halves), BM=64, k-chunk = 32
#define LDA_S 40               // 32 k + 8 pad
#define LDB_S 136              // 128 n + 8 pad
#define ABUF  (64 * LDA_S)     // 2560 halves / buffer
#define BBUF  (32 * LDB_S)     // 4352 halves / buffer

// ---------------- Gate logits: split-K fp32 GEMM (KSPLIT=8) + cnt zeroing ----------------
__global__ __launch_bounds__(256)
void gate_logits_kernel(const float* __restrict__ x, const float* __restrict__ gw,
                        float* __restrict__ logP)
{
    __shared__ float xs[16][65];
    __shared__ float gws[64][65];
    if (blockIdx.x == 0 && blockIdx.y == 0 && threadIdx.x < NEXP)
        g_cnt[threadIdx.x] = 0;

    int m0 = blockIdx.x * 16;
    int kb = blockIdx.y * KSEG;
    int tid = threadIdx.x;
    int m = tid & 15, n4 = tid >> 4;
    float acc[4] = {};

    for (int k0 = kb; k0 < kb + KSEG; k0 += 64) {
        {
            int r = tid >> 4, c = (tid & 15) * 4;
            float4 v = *(const float4*)(x + (size_t)(m0 + r) * HDIM + k0 + c);
            xs[r][c] = v.x; xs[r][c + 1] = v.y; xs[r][c + 2] = v.z; xs[r][c + 3] = v.w;
        }
        #pragma unroll
        for (int i = 0; i < 4; i++) {
            int idx = tid + i * 256;
            int r = idx >> 4, c = (idx & 15) * 4;
            float4 v = *(const float4*)(gw + (size_t)r * HDIM + k0 + c);
            gws[r][c] = v.x; gws[r][c + 1] = v.y; gws[r][c + 2] = v.z; gws[r][c + 3] = v.w;
        }
        __syncthreads();
        #pragma unroll 8
        for (int k = 0; k < 64; k++) {
            float a = xs[m][k];
            acc[0] = fmaf(a, gws[n4 * 4 + 0][k], acc[0]);
            acc[1] = fmaf(a, gws[n4 * 4 + 1][k], acc[1]);
            acc[2] = fmaf(a, gws[n4 * 4 + 2][k], acc[2]);
            acc[3] = fmaf(a, gws[n4 * 4 + 3][k], acc[3]);
        }
        __syncthreads();
    }
    float* dst = logP + ((size_t)blockIdx.y * T_TOK + m0 + m) * NEXP + n4 * 4;
    #pragma unroll
    for (int j = 0; j < 4; j++) dst[j] = acc[j];
}

// ---------------- Top-k selection + slot assignment ----------------
__global__ __launch_bounds__(256)
void topk_kernel(const float* __restrict__ logP, const float* __restrict__ bias)
{
    __shared__ float scores[4][NEXP];
    __shared__ float sc[4][NEXP];
    int tid = threadIdx.x;
    int tk = tid >> 6, tl = tid & 63;
    int t = blockIdx.x * 4 + tk;

    float lg = 0.f;
    #pragma unroll
    for (int ky = 0; ky < KSPLIT; ky++)
        lg += logP[((size_t)ky * T_TOK + t) * NEXP + tl];
    float s = 1.f / (1.f + expf(-lg));
    scores[tk][tl] = s;
    sc[tk][tl] = s + bias[tl];
    __syncthreads();

    if (tl == 0) {
        float gs[NGRP];
        for (int gi = 0; gi < NGRP; gi++) {
            float m1 = -1e30f, m2 = -1e30f;
            for (int j = 0; j < 8; j++) {
                float v = sc[tk][gi * 8 + j];
                if (v > m1) { m2 = m1; m1 = v; } else if (v > m2) m2 = v;
            }
            gs[gi] = m1 + m2;
        }
        bool gsel[NGRP];
        for (int gi = 0; gi < NGRP; gi++) gsel[gi] = false;
        for (int r = 0; r < TOPG; r++) {
            int bi = -1; float bv = -1e30f;
            for (int gi = 0; gi < NGRP; gi++)
                if (!gsel[gi] && gs[gi] > bv) { bv = gs[gi]; bi = gi; }
            gsel[bi] = true;
        }
        float masked[NEXP];
        for (int i = 0; i < NEXP; i++) masked[i] = gsel[i >> 3] ? sc[tk][i] : -1e30f;
        int id[TOPK]; float wsum = 0.f;
        for (int r = 0; r < TOPK; r++) {
            int bi = -1; float bv = -1e30f;
            for (int i = 0; i < NEXP; i++)
                if (masked[i] > bv) { bv = masked[i]; bi = i; }
            masked[bi] = -1e30f;
            id[r] = bi;
            wsum += scores[tk][bi];
        }
        float inv = SCALE / wsum;
        for (int r = 0; r < TOPK; r++) {
            g_ids[t * TOPK + r] = id[r];
            g_wts[t * TOPK + r] = scores[tk][id[r]] * inv;
            g_pos[t * TOPK + r] = atomicAdd(&g_cnt[id[r]], 1);
        }
    }
}

__global__ void scatter16_kernel(const float* __restrict__ x) {
    int i = blockIdx.x;
    int p = g_pos[i];
    if (p >= CAP) return;
    int e = g_ids[i];
    int t = i / TOPK;
    const float4* src = (const float4*)(x + (size_t)t * HDIM);
    __half* dst = g_buf16 + ((size_t)e * CAP + p) * HDIM;
    for (int j = threadIdx.x; j < HDIM / 4; j += blockDim.x) {
        float4 v = src[j];
        __half2 a = __floats2half2_rn(v.x, v.y);
        __half2 b = __floats2half2_rn(v.z, v.w);
        uint2 u = make_uint2(*(uint32_t*)&a, *(uint32_t*)&b);
        *(uint2*)(dst + j * 4) = u;
    }
}

__global__ void conv16_kernel(const float* __restrict__ in, __half* __restrict__ out, int n4) {
    int i = blockIdx.x * blockDim.x + threadIdx.x;
    if (i < n4) {
        float4 v = ((const float4*)in)[i];
        __half2 a = __floats2half2_rn(v.x, v.y);
        __half2 b = __floats2half2_rn(v.z, v.w);
        uint2 u = make_uint2(*(uint32_t*)&a, *(uint32_t*)&b);
        *(uint2*)(out + (size_t)i * 4) = u;
    }
}

static __device__ __forceinline__ uint2 f4h(float4 v) {
    __half2 a = __floats2half2_rn(v.x, v.y);
    __half2 b = __floats2half2_rn(v.z, v.w);
    return make_uint2(*(uint32_t*)&a, *(uint32_t*)&b);
}

// ---------------- Fused up-proj + SiLU*Mul: BM=64, 3 CTAs/SM ----------------
__global__ __launch_bounds__(256, 3)
void gemm13_mma(const __half* __restrict__ A0, int lda, size_t sAe,
                const float* __restrict__ B0, int ldb, size_t sBe, int halfOff,
                __half* __restrict__ C0, int ldc, size_t sCe,
                int Kdim, const int* __restrict__ cnt)
{
    __shared__ __align__(16) __half As[2 * ABUF];
    __shared__ __align__(16) __half Bs[2 * BBUF];

    int e = blockIdx.z;
    int m0 = blockIdx.y * 64;
    if (cnt && m0 >= cnt[e]) return;
    int n0 = blockIdx.x * 64;

    int tid = threadIdx.x;
    int warp = tid >> 5, lane = tid & 31;
    int mw = warp & 1, nw = warp >> 1;   // 2m x 4n warps; warp tile 32m x 16col(g)+16col(u)

    const __half* A = A0 + (size_t)e * sAe + (size_t)m0 * lda;
    const float*  B = B0 + (size_t)e * sBe;
    uint32_t AsU = s2u(As), BsU = s2u(Bs);

    int ar = tid >> 2, acol = (tid & 3) * 8;   // A: 64 rows x 32 halves; 1x16B per thread
    int br = tid >> 3, sg = tid & 7;
    int bcolg = (sg < 4) ? (n0 + sg * 16) : (halfOff + n0 + (sg - 4) * 16);
    int bcols = (sg < 4) ? (sg * 16) : (64 + (sg - 4) * 16);
    const __half* Ag = A + (size_t)ar * lda + acol;
    const float*  Bg = B + (size_t)br * ldb + bcolg;

    float accg[2][2][4] = {}, accu[2][2][4] = {};
    float4 rbf[4];

    auto cpaA = [&](int b, int k0) {
        uint32_t d = AsU + (uint32_t)(b * ABUF + ar * LDA_S + acol) * 2;
        CPA16(d, Ag + k0);
    };
    auto ldgB = [&](int k0) {
        const float4* bp = (const float4*)(Bg + (size_t)k0 * ldb);
        rbf[0] = bp[0]; rbf[1] = bp[1]; rbf[2] = bp[2]; rbf[3] = bp[3];
    };
    auto stsB = [&](int b) {
        uint2 h0 = f4h(rbf[0]), h1 = f4h(rbf[1]), h2 = f4h(rbf[2]), h3 = f4h(rbf[3]);
        uint4* bd = (uint4*)(Bs + b * BBUF + br * LDB_S + bcols);
        bd[0] = make_uint4(h0.x, h0.y, h1.x, h1.y);
        bd[1] = make_uint4(h2.x, h2.y, h3.x, h3.y);
    };

    int NC = Kdim / 32;
    ldgB(0);
    cpaA(0, 0); CP_COMMIT();
    for (int i = 0; i < NC; i++) {
        int b = i & 1;
        stsB(b);
        if (i + 1 < NC) ldgB((i + 1) * 32);
        CP_WAIT0();
        __syncthreads();
        if (i + 1 < NC) {
            cpaA(b ^ 1, (i + 1) * 32);
            CP_COMMIT();
        }

        uint32_t ab = AsU + (uint32_t)(b * ABUF) * 2;
        uint32_t bb = BsU + (uint32_t)(b * BBUF) * 2;
        #pragma unroll
        for (int ks = 0; ks < 32; ks += 16) {
            uint32_t af[2][4];
            #pragma unroll
            for (int mi = 0; mi < 2; mi++) {
                int r = mw * 32 + mi * 16 + (lane & 15);
                LDSM4(af[mi], ab + (uint32_t)(r * LDA_S + ks + (lane >> 4) * 8) * 2);
            }
            uint32_t bgf[4], buf[4];
            int kr = ks + (lane & 15);
            LDSM4T(bgf, bb + (uint32_t)(kr * LDB_S + nw * 16 + (lane >> 4) * 8) * 2);
            LDSM4T(buf, bb + (uint32_t)(kr * LDB_S + 64 + nw * 16 + (lane >> 4) * 8) * 2);
            #pragma unroll
            for (int mi = 0; mi < 2; mi++) {
                MMA16816(accg[mi][0], af[mi], bgf[0], bgf[1]);
                MMA16816(accg[mi][1], af[mi], bgf[2], bgf[3]);
                MMA16816(accu[mi][0], af[mi], buf[0], buf[1]);
                MMA16816(accu[mi][1], af[mi], buf[2], buf[3]);
            }
        }
        // no trailing barrier (writes to this buffer at iter i+2 are post-barrier(i+1))
    }

    int g = lane >> 2, c = lane & 3;
    #pragma unroll
    for (int mi = 0; mi < 2; mi++) {
        #pragma unroll
        for (int j = 0; j < 2; j++) {
            float* G = accg[mi][j];
            float* U = accu[mi][j];
            int col = n0 + nw * 16 + j * 8 + 2 * c;
            int r0 = m0 + mw * 32 + mi * 16 + g;
            float s0 = G[0] / (1.f + expf(-G[0])) * U[0];
            float s1 = G[1] / (1.f + expf(-G[1])) * U[1];
            float s2 = G[2] / (1.f + expf(-G[2])) * U[2];
            float s3 = G[3] / (1.f + expf(-G[3])) * U[3];
            *(__half2*)(C0 + (size_t)e * sCe + (size_t)r0 * ldc + col) = __floats2half2_rn(s0, s1);
            *(__half2*)(C0 + (size_t)e * sCe + (size_t)(r0 + 8) * ldc + col) = __floats2half2_rn(s2, s3);
        }
    }
}

// ---------------- Plain GEMM: BM=64, 3 CTAs/SM, templated out ----------------
template <typename OutT>
__global__ __launch_bounds__(256, 3)
void gemm2_mma(const __half* __restrict__ A0, int lda, size_t sAe,
               const float* __restrict__ B0, int ldb, size_t sBe,
               OutT* __restrict__ C0, int ldc, size_t sCe,
               int Kdim, const int* __restrict__ cnt)
{
    __shared__ __align__(16) __half As[2 * ABUF];
    __shared__ __align__(16) __half Bs[2 * BBUF];

    int e = blockIdx.z;
    int m0 = blockIdx.y * 64;
    if (cnt && m0 >= cnt[e]) return;
    int n0 = blockIdx.x * 128;

    int tid = threadIdx.x;
    int warp = tid >> 5, lane = tid & 31;
    int mw = warp & 1, nw = warp >> 1;   // warp tile 32m x 32n

    const __half* A = A0 + (size_t)e * sAe + (size_t)m0 * lda;
    const float*  B = B0 + (size_t)e * sBe;
    uint32_t AsU = s2u(As), BsU = s2u(Bs);

    int ar = tid >> 2, acol = (tid & 3) * 8;
    int br = tid >> 3, sg = tid & 7;
    const __half* Ag = A + (size_t)ar * lda + acol;
    const float*  Bg = B + (size_t)br * ldb + n0 + sg * 16;

    float acc[2][4][4] = {};
    float4 rbf[4];

    auto cpaA = [&](int b, int k0) {
        uint32_t d = AsU + (uint32_t)(b * ABUF + ar * LDA_S + acol) * 2;
        CPA16(d, Ag + k0);
    };
    auto ldgB = [&](int k0) {
        const float4* bp = (const float4*)(Bg + (size_t)k0 * ldb);
        rbf[0] = bp[0]; rbf[1] = bp[1]; rbf[2] = bp[2]; rbf[3] = bp[3];
    };
    auto stsB = [&](int b) {
        uint2 h0 = f4h(rbf[0]), h1 = f4h(rbf[1]), h2 = f4h(rbf[2]), h3 = f4h(rbf[3]);
        uint4* bd = (uint4*)(Bs + b * BBUF + br * LDB_S + sg * 16);
        bd[0] = make_uint4(h0.x, h0.y, h1.x, h1.y);
        bd[1] = make_uint4(h2.x, h2.y, h3.x, h3.y);
    };

    int NC = Kdim / 32;
    ldgB(0);
    cpaA(0, 0); CP_COMMIT();
    for (int i = 0; i < NC; i++) {
        int b = i & 1;
        stsB(b);
        if (i + 1 < NC) ldgB((i + 1) * 32);
        CP_WAIT0();
        __syncthreads();
        if (i + 1 < NC) {
            cpaA(b ^ 1, (i + 1) * 32);
            CP_COMMIT();
        }

        uint32_t ab = AsU + (uint32_t)(b * ABUF) * 2;
        uint32_t bb = BsU + (uint32_t)(b * BBUF) * 2;
        #pragma unroll
        for (int ks = 0; ks < 32; ks += 16) {
            uint32_t af[2][4];
            #pragma unroll
            for (int mi = 0; mi < 2; mi++) {
                int r = mw * 32 + mi * 16 + (lane & 15);
                LDSM4(af[mi], ab + (uint32_t)(r * LDA_S + ks + (lane >> 4) * 8) * 2);
            }
            uint32_t bf0[4], bf1[4];
            int kr = ks + (lane & 15);
            LDSM4T(bf0, bb + (uint32_t)(kr * LDB_S + nw * 32 + (lane >> 4) * 8) * 2);
            LDSM4T(bf1, bb + (uint32_t)(kr * LDB_S + nw * 32 + 16 + (lane >> 4) * 8) * 2);
            #pragma unroll
            for (int mi = 0; mi < 2; mi++) {
                MMA16816(acc[mi][0], af[mi], bf0[0], bf0[1]);
                MMA16816(acc[mi][1], af[mi], bf0[2], bf0[3]);
                MMA16816(acc[mi][2], af[mi], bf1[0], bf1[1]);
                MMA16816(acc[mi][3], af[mi], bf1[2], bf1[3]);
            }
        }
        // no trailing barrier
    }

    int g = lane >> 2, c = lane & 3;
    #pragma unroll
    for (int mi = 0; mi < 2; mi++) {
        #pragma unroll
        for (int j = 0; j < 4; j++) {
            float* D = acc[mi][j];
            int col = n0 + nw * 32 + j * 8 + 2 * c;
            int r0 = m0 + mw * 32 + mi * 16 + g;
            OutT* Cb = C0 + (size_t)e * sCe;
            if constexpr (sizeof(OutT) == 4) {
                *(float2*)((float*)Cb + (size_t)r0 * ldc + col) = make_float2(D[0], D[1]);
                *(float2*)((float*)Cb + (size_t)(r0 + 8) * ldc + col) = make_float2(D[2], D[3]);
            } else {
                *(__half2*)((__half*)Cb + (size_t)r0 * ldc + col) = __floats2half2_rn(D[0], D[1]);
                *(__half2*)((__half*)Cb + (size_t)(r0 + 8) * ldc + col) = __floats2half2_rn(D[2], D[3]);
            }
        }
    }
}

// ---------------- Combine (eo fp16) ----------------
__global__ void combine_kernel(float* __restrict__ out) {
    int t = blockIdx.x;
    int h = threadIdx.x;
    int ids[TOPK], pos[TOPK]; float w[TOPK];
    #pragma unroll
    for (int k = 0; k < TOPK; k++) {
        ids[k] = g_ids[t * TOPK + k];
        pos[k] = g_pos[t * TOPK + k];
        w[k]   = g_wts[t * TOPK + k];
    }
    float4* o4 = (float4*)(out + (size_t)t * HDIM);
    float4 acc = o4[h];
    #pragma unroll
    for (int k = 0; k < TOPK; k++) {
        if (pos[k] < CAP) {
            const uint2* v2 = (const uint2*)(g_eo16 + ((size_t)ids[k] * CAP + pos[k]) * HDIM);
            uint2 u = v2[h];
            float2 fa = __half22float2(*(__half2*)&u.x);
            float2 fb = __half22float2(*(__half2*)&u.y);
            acc.x = fmaf(w[k], fa.x, acc.x);
            acc.y = fmaf(w[k], fa.y, acc.y);
            acc.z = fmaf(w[k], fb.x, acc.z);
            acc.w = fmaf(w[k], fb.y, acc.w);
        }
    }
    o4[h] = acc;
}

// ---------------- Launch ----------------
extern "C" void kernel_launch(void* const* d_in, const int* in_sizes, int n_in,
                              void* d_out, int out_size)
{
    const float* x      = (const float*)d_in[0];
    const float* gate_w = (const float*)d_in[1];
    const float* bias   = (const float*)d_in[2];
    const float* w13    = (const float*)d_in[3];
    const float* w2     = (const float*)d_in[4];
    const float* sw13   = (const float*)d_in[5];
    const float* sw2    = (const float*)d_in[6];
    float* out = (float*)d_out;

    __half *buf16, *act16, *eo16, *x16, *acts16;
    float* logP; int* cnt;
    cudaGetSymbolAddress((void**)&buf16,  g_buf16);
    cudaGetSymbolAddress((void**)&act16,  g_act16);
    cudaGetSymbolAddress((void**)&eo16,   g_eo16);
    cudaGetSymbolAddress((void**)&x16,    g_x16);
    cudaGetSymbolAddress((void**)&acts16, g_acts16);
    cudaGetSymbolAddress((void**)&logP,   g_logP);
    cudaGetSymbolAddress((void**)&cnt,    g_cnt);

    static cudaStream_t s2 = nullptr;
    static cudaEvent_t evA = nullptr, evSh = nullptr;
    if (!s2) {
        cudaStreamCreateWithFlags(&s2, cudaStreamNonBlocking);
        cudaEventCreateWithFlags(&evA,  cudaEventDisableTiming);
        cudaEventCreateWithFlags(&evSh, cudaEventDisableTiming);
    }

    // fork point
    cudaEventRecord(evA, 0);
    cudaStreamWaitEvent(s2, evA, 0);

    // ---- main stream first (submission order keeps ncu window on routed gemm13) ----
    gate_logits_kernel<<<dim3(T_TOK / 16, KSPLIT), 256>>>(x, gate_w, logP);   // #1 (zeroes cnt)
    topk_kernel<<<T_TOK / 4, 256>>>(logP, bias);                              // #2
    scatter16_kernel<<<T_TOK * TOPK, 128>>>(x);                               // #3

    gemm13_mma<<<dim3(FDIM / 64, CAP / 64, NEXP), 256>>>(                     // #4 <- profile target
        buf16, HDIM, (size_t)CAP * HDIM,
        w13, 2 * FDIM, (size_t)HDIM * 2 * FDIM, FDIM,
        act16, FDIM, (size_t)CAP * FDIM,
        HDIM, cnt);

    gemm2_mma<__half><<<dim3(HDIM / 128, CAP / 64, NEXP), 256>>>(             // #5
        act16, FDIM, (size_t)CAP * FDIM,
        w2, HDIM, (size_t)FDIM * HDIM,
        eo16, HDIM, (size_t)CAP * HDIM,
        FDIM, cnt);

    // ---- side stream: shared-expert chain ----
    conv16_kernel<<<(T_TOK * HDIM / 4 + 255) / 256, 256, 0, s2>>>(x, x16, T_TOK * HDIM / 4);
    gemm13_mma<<<dim3(FSH / 64, T_TOK / 64, 1), 256, 0, s2>>>(
        x16, HDIM, 0, sw13, 2 * FSH, 0, FSH, acts16, FSH, 0, HDIM, nullptr);
    gemm2_mma<float><<<dim3(HDIM / 128, T_TOK / 64, 1), 256, 0, s2>>>(
        acts16, FSH, 0, sw2, HDIM, 0, out, HDIM, 0, FSH, nullptr);
    cudaEventRecord(evSh, s2);

    // join shared branch, then combine
    cudaStreamWaitEvent(0, evSh, 0);
    combine_kernel<<<T_TOK, 256>>>(out);
}

// round 13
// speedup vs baseline: 1.4597x; 1.4597x over previous
#include <cuda_runtime.h>
#include <cuda_fp16.h>
#include <cstdint>
#include <math.h>

// ---------------- Problem constants ----------------
#define T_TOK   1024
#define HDIM    1024
#define NEXP    64
#define TOPK    6
#define NGRP    8
#define TOPG    4
#define FDIM    512
#define FSH     1024
#define CAP     384
#define SCALE   2.5f
#define KSPLIT  8
#define KSEG    (HDIM / KSPLIT)   // 128

// ---------------- Device scratch ----------------
__device__ __align__(16) __half g_buf16 [(size_t)NEXP * CAP * HDIM];
__device__ __align__(16) __half g_act16 [(size_t)NEXP * CAP * FDIM];
__device__ __align__(16) __half g_eo16  [(size_t)NEXP * CAP * HDIM];
__device__ __align__(16) __half g_x16   [(size_t)T_TOK * HDIM];
__device__ __align__(16) __half g_acts16[(size_t)T_TOK * FSH];
__device__ __align__(16) float  g_logP  [(size_t)KSPLIT * T_TOK * NEXP];
__device__ int   g_cnt[NEXP];
__device__ int   g_ids[T_TOK * TOPK];
__device__ int   g_pos[T_TOK * TOPK];
__device__ float g_wts[T_TOK * TOPK];

// ---------------- PTX helpers ----------------
static __device__ __forceinline__ uint32_t s2u(const void* p) {
    uint32_t a;
    asm("{ .reg .u64 t; cvta.to.shared.u64 t, %1; cvt.u32.u64 %0, t; }" : "=r"(a) : "l"(p));
    return a;
}
#define CPA16(dst, src) asm volatile("cp.async.cg.shared.global [%0], [%1], 16;" :: "r"(dst), "l"(src))
#define CP_COMMIT()     asm volatile("cp.async.commit_group;")
#define CP_WAIT0()      asm volatile("cp.async.wait_group 0;")
#define LDSM4(r, addr) \
    asm volatile("ldmatrix.sync.aligned.m8n8.x4.shared.b16 {%0,%1,%2,%3}, [%4];" \
        : "=r"((r)[0]), "=r"((r)[1]), "=r"((r)[2]), "=r"((r)[3]) : "r"(addr))
#define LDSM4T(r, addr) \
    asm volatile("ldmatrix.sync.aligned.m8n8.x4.trans.shared.b16 {%0,%1,%2,%3}, [%4];" \
        : "=r"((r)[0]), "=r"((r)[1]), "=r"((r)[2]), "=r"((r)[3]) : "r"(addr))
#define MMA16816(d, a, b0, b1) \
    asm volatile("mma.sync.aligned.m16n8k16.row.col.f32.f16.f16.f32 " \
        "{%0,%1,%2,%3}, {%4,%5,%6,%7}, {%8,%9}, {%0,%1,%2,%3};" \
        : "+f"((d)[0]), "+f"((d)[1]), "+f"((d)[2]), "+f"((d)[3]) \
        : "r"((a)[0]), "r"((a)[1]), "r"((a)[2]), "r"((a)[3]), "r"(b0), "r"(b1))

// SMEM tile geometry (halves), BM=128, k-chunk = 32
#define LDA_S 40
#define LDB_S 136
#define ABUF  (128 * LDA_S)
#define BBUF  (32 * LDB_S)

// ---------------- Gate logits: split-K fp32 GEMM (KSPLIT=8) + cnt zeroing ----------------
__global__ __launch_bounds__(256)
void gate_logits_kernel(const float* __restrict__ x, const float* __restrict__ gw,
                        float* __restrict__ logP)
{
    __shared__ float xs[16][65];
    __shared__ float gws[64][65];
    if (blockIdx.x == 0 && blockIdx.y == 0 && threadIdx.x < NEXP)
        g_cnt[threadIdx.x] = 0;

    int m0 = blockIdx.x * 16;
    int kb = blockIdx.y * KSEG;
    int tid = threadIdx.x;
    int m = tid & 15, n4 = tid >> 4;
    float acc[4] = {};

    for (int k0 = kb; k0 < kb + KSEG; k0 += 64) {
        {
            int r = tid >> 4, c = (tid & 15) * 4;
            float4 v = *(const float4*)(x + (size_t)(m0 + r) * HDIM + k0 + c);
            xs[r][c] = v.x; xs[r][c + 1] = v.y; xs[r][c + 2] = v.z; xs[r][c + 3] = v.w;
        }
        #pragma unroll
        for (int i = 0; i < 4; i++) {
            int idx = tid + i * 256;
            int r = idx >> 4, c = (idx & 15) * 4;
            float4 v = *(const float4*)(gw + (size_t)r * HDIM + k0 + c);
            gws[r][c] = v.x; gws[r][c + 1] = v.y; gws[r][c + 2] = v.z; gws[r][c + 3] = v.w;
        }
        __syncthreads();
        #pragma unroll 8
        for (int k = 0; k < 64; k++) {
            float a = xs[m][k];
            acc[0] = fmaf(a, gws[n4 * 4 + 0][k], acc[0]);
            acc[1] = fmaf(a, gws[n4 * 4 + 1][k], acc[1]);
            acc[2] = fmaf(a, gws[n4 * 4 + 2][k], acc[2]);
            acc[3] = fmaf(a, gws[n4 * 4 + 3][k], acc[3]);
        }
        __syncthreads();
    }
    float* dst = logP + ((size_t)blockIdx.y * T_TOK + m0 + m) * NEXP + n4 * 4;
    #pragma unroll
    for (int j = 0; j < 4; j++) dst[j] = acc[j];
}

// ---------------- Top-k selection + slot assignment + fused scatter ----------------
__global__ __launch_bounds__(256)
void topk_kernel(const float* __restrict__ logP, const float* __restrict__ bias,
                 const float* __restrict__ x)
{
    __shared__ float scores[4][NEXP];
    __shared__ float sc[4][NEXP];
    __shared__ int   s_ids[4][TOPK];
    __shared__ int   s_pos[4][TOPK];
    int tid = threadIdx.x;
    int tk = tid >> 6, tl = tid & 63;
    int t0 = blockIdx.x * 4;
    int t = t0 + tk;

    float lg = 0.f;
    #pragma unroll
    for (int ky = 0; ky < KSPLIT; ky++)
        lg += logP[((size_t)ky * T_TOK + t) * NEXP + tl];
    float s = 1.f / (1.f + expf(-lg));
    scores[tk][tl] = s;
    sc[tk][tl] = s + bias[tl];
    __syncthreads();

    if (tl == 0) {
        float gs[NGRP];
        for (int gi = 0; gi < NGRP; gi++) {
            float m1 = -1e30f, m2 = -1e30f;
            for (int j = 0; j < 8; j++) {
                float v = sc[tk][gi * 8 + j];
                if (v > m1) { m2 = m1; m1 = v; } else if (v > m2) m2 = v;
            }
            gs[gi] = m1 + m2;
        }
        bool gsel[NGRP];
        for (int gi = 0; gi < NGRP; gi++) gsel[gi] = false;
        for (int r = 0; r < TOPG; r++) {
            int bi = -1; float bv = -1e30f;
            for (int gi = 0; gi < NGRP; gi++)
                if (!gsel[gi] && gs[gi] > bv) { bv = gs[gi]; bi = gi; }
            gsel[bi] = true;
        }
        float masked[NEXP];
        for (int i = 0; i < NEXP; i++) masked[i] = gsel[i >> 3] ? sc[tk][i] : -1e30f;
        int id[TOPK]; float wsum = 0.f;
        for (int r = 0; r < TOPK; r++) {
            int bi = -1; float bv = -1e30f;
            for (int i = 0; i < NEXP; i++)
                if (masked[i] > bv) { bv = masked[i]; bi = i; }
            masked[bi] = -1e30f;
            id[r] = bi;
            wsum += scores[tk][bi];
        }
        float inv = SCALE / wsum;
        for (int r = 0; r < TOPK; r++) {
            int p = atomicAdd(&g_cnt[id[r]], 1);
            g_ids[t * TOPK + r] = id[r];
            g_wts[t * TOPK + r] = scores[tk][id[r]] * inv;
            g_pos[t * TOPK + r] = p;
            s_ids[tk][r] = id[r];
            s_pos[tk][r] = p;
        }
    }
    __syncthreads();

    // fused scatter: all 256 threads copy 4 tokens x TOPK slots (row = 1024 fp32 -> fp16)
    for (int slot = 0; slot < 4 * TOPK; slot++) {
        int tt = slot / TOPK, r = slot % TOPK;
        int p = s_pos[tt][r];
        if (p >= CAP) continue;
        int e = s_ids[tt][r];
        const float4* src = (const float4*)(x + (size_t)(t0 + tt) * HDIM);
        __half* dst = g_buf16 + ((size_t)e * CAP + p) * HDIM;
        float4 v = src[tid];                       // 256 threads x 4 floats = 1024
        __half2 a = __floats2half2_rn(v.x, v.y);
        __half2 b = __floats2half2_rn(v.z, v.w);
        uint2 u = make_uint2(*(uint32_t*)&a, *(uint32_t*)&b);
        *(uint2*)(dst + tid * 4) = u;
    }
}

__global__ void conv16_kernel(const float* __restrict__ in, __half* __restrict__ out, int n4) {
    int i = blockIdx.x * blockDim.x + threadIdx.x;
    if (i < n4) {
        float4 v = ((const float4*)in)[i];
        __half2 a = __floats2half2_rn(v.x, v.y);
        __half2 b = __floats2half2_rn(v.z, v.w);
        uint2 u = make_uint2(*(uint32_t*)&a, *(uint32_t*)&b);
        *(uint2*)(out + (size_t)i * 4) = u;
    }
}

static __device__ __forceinline__ uint2 f4h(float4 v) {
    __half2 a = __floats2half2_rn(v.x, v.y);
    __half2 b = __floats2half2_rn(v.z, v.w);
    return make_uint2(*(uint32_t*)&a, *(uint32_t*)&b);
}

// ---------------- Fused up-proj + SiLU*Mul: BM=128, 2 CTAs/SM (R11 config) ----------------
__global__ __launch_bounds__(256, 2)
void gemm13_mma(const __half* __restrict__ A0, int lda, size_t sAe,
                const float* __restrict__ B0, int ldb, size_t sBe, int halfOff,
                __half* __restrict__ C0, int ldc, size_t sCe,
                int Kdim, const int* __restrict__ cnt)
{
    __shared__ __align__(16) __half As[2 * ABUF];
    __shared__ __align__(16) __half Bs[2 * BBUF];

    int e = blockIdx.z;
    int m0 = blockIdx.y * 128;
    if (cnt && m0 >= cnt[e]) return;
    int n0 = blockIdx.x * 64;

    int tid = threadIdx.x;
    int warp = tid >> 5, lane = tid & 31;
    int mw = warp & 1, nw = warp >> 1;

    const __half* A = A0 + (size_t)e * sAe + (size_t)m0 * lda;
    const float*  B = B0 + (size_t)e * sBe;
    uint32_t AsU = s2u(As), BsU = s2u(Bs);

    int ar = tid >> 1, acol = (tid & 1) * 16;
    int br = tid >> 3, sg = tid & 7;
    int bcolg = (sg < 4) ? (n0 + sg * 16) : (halfOff + n0 + (sg - 4) * 16);
    int bcols = (sg < 4) ? (sg * 16) : (64 + (sg - 4) * 16);
    const __half* Ag = A + (size_t)ar * lda + acol;
    const float*  Bg = B + (size_t)br * ldb + bcolg;

    float accg[4][2][4] = {}, accu[4][2][4] = {};
    float4 rbf[4];

    auto cpaA = [&](int b, int k0) {
        uint32_t d = AsU + (uint32_t)(b * ABUF + ar * LDA_S + acol) * 2;
        const __half* s = Ag + k0;
        CPA16(d, s);
        CPA16(d + 16, s + 8);
    };
    auto ldgB = [&](int k0) {
        const float4* bp = (const float4*)(Bg + (size_t)k0 * ldb);
        rbf[0] = bp[0]; rbf[1] = bp[1]; rbf[2] = bp[2]; rbf[3] = bp[3];
    };
    auto stsB = [&](int b) {
        uint2 h0 = f4h(rbf[0]), h1 = f4h(rbf[1]), h2 = f4h(rbf[2]), h3 = f4h(rbf[3]);
        uint4* bd = (uint4*)(Bs + b * BBUF + br * LDB_S + bcols);
        bd[0] = make_uint4(h0.x, h0.y, h1.x, h1.y);
        bd[1] = make_uint4(h2.x, h2.y, h3.x, h3.y);
    };

    int NC = Kdim / 32;
    ldgB(0);
    cpaA(0, 0); CP_COMMIT();
    for (int i = 0; i < NC; i++) {
        int b = i & 1;
        stsB(b);
        if (i + 1 < NC) ldgB((i + 1) * 32);
        CP_WAIT0();
        __syncthreads();
        if (i + 1 < NC) {
            cpaA(b ^ 1, (i + 1) * 32);
            CP_COMMIT();
        }

        uint32_t ab = AsU + (uint32_t)(b * ABUF) * 2;
        uint32_t bb = BsU + (uint32_t)(b * BBUF) * 2;
        #pragma unroll
        for (int ks = 0; ks < 32; ks += 16) {
            uint32_t af[4][4];
            #pragma unroll
            for (int mi = 0; mi < 4; mi++) {
                int r = mw * 64 + mi * 16 + (lane & 15);
                LDSM4(af[mi], ab + (uint32_t)(r * LDA_S + ks + (lane >> 4) * 8) * 2);
            }
            uint32_t bgf[4], buf[4];
            int kr = ks + (lane & 15);
            LDSM4T(bgf, bb + (uint32_t)(kr * LDB_S + nw * 16 + (lane >> 4) * 8) * 2);
            LDSM4T(buf, bb + (uint32_t)(kr * LDB_S + 64 + nw * 16 + (lane >> 4) * 8) * 2);
            #pragma unroll
            for (int mi = 0; mi < 4; mi++) {
                MMA16816(accg[mi][0], af[mi], bgf[0], bgf[1]);
                MMA16816(accg[mi][1], af[mi], bgf[2], bgf[3]);
                MMA16816(accu[mi][0], af[mi], buf[0], buf[1]);
                MMA16816(accu[mi][1], af[mi], buf[2], buf[3]);
            }
        }
        // no trailing barrier (writes to this buffer at iter i+2 are post-barrier(i+1))
    }

    int g = lane >> 2, c = lane & 3;
    #pragma unroll
    for (int mi = 0; mi < 4; mi++) {
        #pragma unroll
        for (int j = 0; j < 2; j++) {
            float* G = accg[mi][j];
            float* U = accu[mi][j];
            int col = n0 + nw * 16 + j * 8 + 2 * c;
            int r0 = m0 + mw * 64 + mi * 16 + g;
            float s0 = G[0] / (1.f + expf(-G[0])) * U[0];
            float s1 = G[1] / (1.f + expf(-G[1])) * U[1];
            float s2 = G[2] / (1.f + expf(-G[2])) * U[2];
            float s3 = G[3] / (1.f + expf(-G[3])) * U[3];
            *(__half2*)(C0 + (size_t)e * sCe + (size_t)r0 * ldc + col) = __floats2half2_rn(s0, s1);
            *(__half2*)(C0 + (size_t)e * sCe + (size_t)(r0 + 8) * ldc + col) = __floats2half2_rn(s2, s3);
        }
    }
}

// ---------------- Plain GEMM: BM=128, 2 CTAs/SM, templated out ----------------
template <typename OutT>
__global__ __launch_bounds__(256, 2)
void gemm2_mma(const __half* __restrict__ A0, int lda, size_t sAe,
               const float* __restrict__ B0, int ldb, size_t sBe,
               OutT* __restrict__ C0, int ldc, size_t sCe,
               int Kdim, const int* __restrict__ cnt)
{
    __shared__ __align__(16) __half As[2 * ABUF];
    __shared__ __align__(16) __half Bs[2 * BBUF];

    int e = blockIdx.z;
    int m0 = blockIdx.y * 128;
    if (cnt && m0 >= cnt[e]) return;
    int n0 = blockIdx.x * 128;

    int tid = threadIdx.x;
    int warp = tid >> 5, lane = tid & 31;
    int mw = warp & 1, nw = warp >> 1;

    const __half* A = A0 + (size_t)e * sAe + (size_t)m0 * lda;
    const float*  B = B0 + (size_t)e * sBe;
    uint32_t AsU = s2u(As), BsU = s2u(Bs);

    int ar = tid >> 1, acol = (tid & 1) * 16;
    int br = tid >> 3, sg = tid & 7;
    const __half* Ag = A + (size_t)ar * lda + acol;
    const float*  Bg = B + (size_t)br * ldb + n0 + sg * 16;

    float acc[4][4][4] = {};
    float4 rbf[4];

    auto cpaA = [&](int b, int k0) {
        uint32_t d = AsU + (uint32_t)(b * ABUF + ar * LDA_S + acol) * 2;
        const __half* s = Ag + k0;
        CPA16(d, s);
        CPA16(d + 16, s + 8);
    };
    auto ldgB = [&](int k0) {
        const float4* bp = (const float4*)(Bg + (size_t)k0 * ldb);
        rbf[0] = bp[0]; rbf[1] = bp[1]; rbf[2] = bp[2]; rbf[3] = bp[3];
    };
    auto stsB = [&](int b) {
        uint2 h0 = f4h(rbf[0]), h1 = f4h(rbf[1]), h2 = f4h(rbf[2]), h3 = f4h(rbf[3]);
        uint4* bd = (uint4*)(Bs + b * BBUF + br * LDB_S + sg * 16);
        bd[0] = make_uint4(h0.x, h0.y, h1.x, h1.y);
        bd[1] = make_uint4(h2.x, h2.y, h3.x, h3.y);
    };

    int NC = Kdim / 32;
    ldgB(0);
    cpaA(0, 0); CP_COMMIT();
    for (int i = 0; i < NC; i++) {
        int b = i & 1;
        stsB(b);
        if (i + 1 < NC) ldgB((i + 1) * 32);
        CP_WAIT0();
        __syncthreads();
        if (i + 1 < NC) {
            cpaA(b ^ 1, (i + 1) * 32);
            CP_COMMIT();
        }

        uint32_t ab = AsU + (uint32_t)(b * ABUF) * 2;
        uint32_t bb = BsU + (uint32_t)(b * BBUF) * 2;
        #pragma unroll
        for (int ks = 0; ks < 32; ks += 16) {
            uint32_t af[4][4];
            #pragma unroll
            for (int mi = 0; mi < 4; mi++) {
                int r = mw * 64 + mi * 16 + (lane & 15);
                LDSM4(af[mi], ab + (uint32_t)(r * LDA_S + ks + (lane >> 4) * 8) * 2);
            }
            uint32_t bf0[4], bf1[4];
            int kr = ks + (lane & 15);
            LDSM4T(bf0, bb + (uint32_t)(kr * LDB_S + nw * 32 + (lane >> 4) * 8) * 2);
            LDSM4T(bf1, bb + (uint32_t)(kr * LDB_S + nw * 32 + 16 + (lane >> 4) * 8) * 2);
            #pragma unroll
            for (int mi = 0; mi < 4; mi++) {
                MMA16816(acc[mi][0], af[mi], bf0[0], bf0[1]);
                MMA16816(acc[mi][1], af[mi], bf0[2], bf0[3]);
                MMA16816(acc[mi][2], af[mi], bf1[0], bf1[1]);
                MMA16816(acc[mi][3], af[mi], bf1[2], bf1[3]);
            }
        }
        // no trailing barrier
    }

    int g = lane >> 2, c = lane & 3;
    #pragma unroll
    for (int mi = 0; mi < 4; mi++) {
        #pragma unroll
        for (int j = 0; j < 4; j++) {
            float* D = acc[mi][j];
            int col = n0 + nw * 32 + j * 8 + 2 * c;
            int r0 = m0 + mw * 64 + mi * 16 + g;
            OutT* Cb = C0 + (size_t)e * sCe;
            if constexpr (sizeof(OutT) == 4) {
                *(float2*)((float*)Cb + (size_t)r0 * ldc + col) = make_float2(D[0], D[1]);
                *(float2*)((float*)Cb + (size_t)(r0 + 8) * ldc + col) = make_float2(D[2], D[3]);
            } else {
                *(__half2*)((__half*)Cb + (size_t)r0 * ldc + col) = __floats2half2_rn(D[0], D[1]);
                *(__half2*)((__half*)Cb + (size_t)(r0 + 8) * ldc + col) = __floats2half2_rn(D[2], D[3]);
            }
        }
    }
}

// ---------------- Combine (eo fp16) ----------------
__global__ void combine_kernel(float* __restrict__ out) {
    int t = blockIdx.x;
    int h = threadIdx.x;
    int ids[TOPK], pos[TOPK]; float w[TOPK];
    #pragma unroll
    for (int k = 0; k < TOPK; k++) {
        ids[k] = g_ids[t * TOPK + k];
        pos[k] = g_pos[t * TOPK + k];
        w[k]   = g_wts[t * TOPK + k];
    }
    float4* o4 = (float4*)(out + (size_t)t * HDIM);
    float4 acc = o4[h];
    #pragma unroll
    for (int k = 0; k < TOPK; k++) {
        if (pos[k] < CAP) {
            const uint2* v2 = (const uint2*)(g_eo16 + ((size_t)ids[k] * CAP + pos[k]) * HDIM);
            uint2 u = v2[h];
            float2 fa = __half22float2(*(__half2*)&u.x);
            float2 fb = __half22float2(*(__half2*)&u.y);
            acc.x = fmaf(w[k], fa.x, acc.x);
            acc.y = fmaf(w[k], fa.y, acc.y);
            acc.z = fmaf(w[k], fb.x, acc.z);
            acc.w = fmaf(w[k], fb.y, acc.w);
        }
    }
    o4[h] = acc;
}

// ---------------- Launch ----------------
extern "C" void kernel_launch(void* const* d_in, const int* in_sizes, int n_in,
                              void* d_out, int out_size)
{
    const float* x      = (const float*)d_in[0];
    const float* gate_w = (const float*)d_in[1];
    const float* bias   = (const float*)d_in[2];
    const float* w13    = (const float*)d_in[3];
    const float* w2     = (const float*)d_in[4];
    const float* sw13   = (const float*)d_in[5];
    const float* sw2    = (const float*)d_in[6];
    float* out = (float*)d_out;

    __half *buf16, *act16, *eo16, *x16, *acts16;
    float* logP; int* cnt;
    cudaGetSymbolAddress((void**)&buf16,  g_buf16);
    cudaGetSymbolAddress((void**)&act16,  g_act16);
    cudaGetSymbolAddress((void**)&eo16,   g_eo16);
    cudaGetSymbolAddress((void**)&x16,    g_x16);
    cudaGetSymbolAddress((void**)&acts16, g_acts16);
    cudaGetSymbolAddress((void**)&logP,   g_logP);
    cudaGetSymbolAddress((void**)&cnt,    g_cnt);

    static cudaStream_t s2 = nullptr;
    static cudaEvent_t evA = nullptr, evSh = nullptr;
    if (!s2) {
        cudaStreamCreateWithFlags(&s2, cudaStreamNonBlocking);
        cudaEventCreateWithFlags(&evA,  cudaEventDisableTiming);
        cudaEventCreateWithFlags(&evSh, cudaEventDisableTiming);
    }

    // fork point
    cudaEventRecord(evA, 0);
    cudaStreamWaitEvent(s2, evA, 0);

    // ---- main stream first ----
    gate_logits_kernel<<<dim3(T_TOK / 16, KSPLIT), 256>>>(x, gate_w, logP);   // #1 (zeroes cnt)
    topk_kernel<<<T_TOK / 4, 256>>>(logP, bias, x);                           // #2 (+fused scatter)

    gemm13_mma<<<dim3(FDIM / 64, CAP / 128, NEXP), 256>>>(                    // #3 <- profile target
        buf16, HDIM, (size_t)CAP * HDIM,
        w13, 2 * FDIM, (size_t)HDIM * 2 * FDIM, FDIM,
        act16, FDIM, (size_t)CAP * FDIM,
        HDIM, cnt);

    gemm2_mma<__half><<<dim3(HDIM / 128, CAP / 128, NEXP), 256>>>(            // #4
        act16, FDIM, (size_t)CAP * FDIM,
        w2, HDIM, (size_t)FDIM * HDIM,
        eo16, HDIM, (size_t)CAP * HDIM,
        FDIM, cnt);

    // ---- side stream: shared-expert chain ----
    conv16_kernel<<<(T_TOK * HDIM / 4 + 255) / 256, 256, 0, s2>>>(x, x16, T_TOK * HDIM / 4);
    gemm13_mma<<<dim3(FSH / 64, T_TOK / 128, 1), 256, 0, s2>>>(
        x16, HDIM, 0, sw13, 2 * FSH, 0, FSH, acts16, FSH, 0, HDIM, nullptr);
    gemm2_mma<float><<<dim3(HDIM / 128, T_TOK / 128, 1), 256, 0, s2>>>(
        acts16, FSH, 0, sw2, HDIM, 0, out, HDIM, 0, FSH, nullptr);
    cudaEventRecord(evSh, s2);

    // join shared branch, then combine
    cudaStreamWaitEvent(0, evSh, 0);
    combine_kernel<<<T_TOK, 256>>>(out);
}

// round 14
// speedup vs baseline: 1.5462x; 1.0592x over previous
#include <cuda_runtime.h>
#include <cuda_fp16.h>
#include <cstdint>
#include <math.h>

// ---------------- Problem constants ----------------
#define T_TOK   1024
#define HDIM    1024
#define NEXP    64
#define TOPK    6
#define NGRP    8
#define TOPG    4
#define FDIM    512
#define FSH     1024
#define CAP     384
#define SCALE   2.5f
#define KSPLIT  8
#define KSEG    (HDIM / KSPLIT)   // 128

// ---------------- Device scratch ----------------
__device__ __align__(16) __half g_buf16 [(size_t)NEXP * CAP * HDIM];
__device__ __align__(16) __half g_act16 [(size_t)NEXP * CAP * FDIM];
__device__ __align__(16) __half g_eo16  [(size_t)NEXP * CAP * HDIM];
__device__ __align__(16) __half g_x16   [(size_t)T_TOK * HDIM];
__device__ __align__(16) __half g_acts16[(size_t)T_TOK * FSH];
__device__ __align__(16) float  g_logP  [(size_t)KSPLIT * T_TOK * NEXP];
__device__ int   g_cnt[NEXP];
__device__ int   g_ids[T_TOK * TOPK];
__device__ int   g_pos[T_TOK * TOPK];
__device__ float g_wts[T_TOK * TOPK];

// ---------------- PTX helpers ----------------
static __device__ __forceinline__ uint32_t s2u(const void* p) {
    uint32_t a;
    asm("{ .reg .u64 t; cvta.to.shared.u64 t, %1; cvt.u32.u64 %0, t; }" : "=r"(a) : "l"(p));
    return a;
}
#define CPA16(dst, src) asm volatile("cp.async.cg.shared.global [%0], [%1], 16;" :: "r"(dst), "l"(src))
#define CP_COMMIT()     asm volatile("cp.async.commit_group;")
#define CP_WAIT0()      asm volatile("cp.async.wait_group 0;")
#define CP_WAIT1()      asm volatile("cp.async.wait_group 1;")
#define LDSM4(r, addr) \
    asm volatile("ldmatrix.sync.aligned.m8n8.x4.shared.b16 {%0,%1,%2,%3}, [%4];" \
        : "=r"((r)[0]), "=r"((r)[1]), "=r"((r)[2]), "=r"((r)[3]) : "r"(addr))
#define LDSM4T(r, addr) \
    asm volatile("ldmatrix.sync.aligned.m8n8.x4.trans.shared.b16 {%0,%1,%2,%3}, [%4];" \
        : "=r"((r)[0]), "=r"((r)[1]), "=r"((r)[2]), "=r"((r)[3]) : "r"(addr))
#define MMA16816(d, a, b0, b1) \
    asm volatile("mma.sync.aligned.m16n8k16.row.col.f32.f16.f16.f32 " \
        "{%0,%1,%2,%3}, {%4,%5,%6,%7}, {%8,%9}, {%0,%1,%2,%3};" \
        : "+f"((d)[0]), "+f"((d)[1]), "+f"((d)[2]), "+f"((d)[3]) \
        : "r"((a)[0]), "r"((a)[1]), "r"((a)[2]), "r"((a)[3]), "r"(b0), "r"(b1))

// SMEM tile geometry (halves), BM=128, k-chunk = 32; 3 A buffers + 2 B buffers
#define LDA_S 40
#define LDB_S 136
#define ABUF  (128 * LDA_S)   // 5120 halves = 10240 B
#define BBUF  (32 * LDB_S)    // 4352 halves =  8704 B
// static SMEM: 3*10240 + 2*8704 = 48128 B  (<= 48 KB)

// ---------------- Gate logits: split-K fp32 GEMM (KSPLIT=8) + cnt zeroing ----------------
__global__ __launch_bounds__(256)
void gate_logits_kernel(const float* __restrict__ x, const float* __restrict__ gw,
                        float* __restrict__ logP)
{
    __shared__ float xs[16][65];
    __shared__ float gws[64][65];
    if (blockIdx.x == 0 && blockIdx.y == 0 && threadIdx.x < NEXP)
        g_cnt[threadIdx.x] = 0;

    int m0 = blockIdx.x * 16;
    int kb = blockIdx.y * KSEG;
    int tid = threadIdx.x;
    int m = tid & 15, n4 = tid >> 4;
    float acc[4] = {};

    for (int k0 = kb; k0 < kb + KSEG; k0 += 64) {
        {
            int r = tid >> 4, c = (tid & 15) * 4;
            float4 v = *(const float4*)(x + (size_t)(m0 + r) * HDIM + k0 + c);
            xs[r][c] = v.x; xs[r][c + 1] = v.y; xs[r][c + 2] = v.z; xs[r][c + 3] = v.w;
        }
        #pragma unroll
        for (int i = 0; i < 4; i++) {
            int idx = tid + i * 256;
            int r = idx >> 4, c = (idx & 15) * 4;
            float4 v = *(const float4*)(gw + (size_t)r * HDIM + k0 + c);
            gws[r][c] = v.x; gws[r][c + 1] = v.y; gws[r][c + 2] = v.z; gws[r][c + 3] = v.w;
        }
        __syncthreads();
        #pragma unroll 8
        for (int k = 0; k < 64; k++) {
            float a = xs[m][k];
            acc[0] = fmaf(a, gws[n4 * 4 + 0][k], acc[0]);
            acc[1] = fmaf(a, gws[n4 * 4 + 1][k], acc[1]);
            acc[2] = fmaf(a, gws[n4 * 4 + 2][k], acc[2]);
            acc[3] = fmaf(a, gws[n4 * 4 + 3][k], acc[3]);
        }
        __syncthreads();
    }
    float* dst = logP + ((size_t)blockIdx.y * T_TOK + m0 + m) * NEXP + n4 * 4;
    #pragma unroll
    for (int j = 0; j < 4; j++) dst[j] = acc[j];
}

// ---------------- Top-k selection + slot assignment + fused scatter ----------------
__global__ __launch_bounds__(256)
void topk_kernel(const float* __restrict__ logP, const float* __restrict__ bias,
                 const float* __restrict__ x)
{
    __shared__ float scores[4][NEXP];
    __shared__ float sc[4][NEXP];
    __shared__ int   s_ids[4][TOPK];
    __shared__ int   s_pos[4][TOPK];
    int tid = threadIdx.x;
    int tk = tid >> 6, tl = tid & 63;
    int t0 = blockIdx.x * 4;
    int t = t0 + tk;

    float lg = 0.f;
    #pragma unroll
    for (int ky = 0; ky < KSPLIT; ky++)
        lg += logP[((size_t)ky * T_TOK + t) * NEXP + tl];
    float s = 1.f / (1.f + expf(-lg));
    scores[tk][tl] = s;
    sc[tk][tl] = s + bias[tl];
    __syncthreads();

    if (tl == 0) {
        float gs[NGRP];
        for (int gi = 0; gi < NGRP; gi++) {
            float m1 = -1e30f, m2 = -1e30f;
            for (int j = 0; j < 8; j++) {
                float v = sc[tk][gi * 8 + j];
                if (v > m1) { m2 = m1; m1 = v; } else if (v > m2) m2 = v;
            }
            gs[gi] = m1 + m2;
        }
        bool gsel[NGRP];
        for (int gi = 0; gi < NGRP; gi++) gsel[gi] = false;
        for (int r = 0; r < TOPG; r++) {
            int bi = -1; float bv = -1e30f;
            for (int gi = 0; gi < NGRP; gi++)
                if (!gsel[gi] && gs[gi] > bv) { bv = gs[gi]; bi = gi; }
            gsel[bi] = true;
        }
        float masked[NEXP];
        for (int i = 0; i < NEXP; i++) masked[i] = gsel[i >> 3] ? sc[tk][i] : -1e30f;
        int id[TOPK]; float wsum = 0.f;
        for (int r = 0; r < TOPK; r++) {
            int bi = -1; float bv = -1e30f;
            for (int i = 0; i < NEXP; i++)
                if (masked[i] > bv) { bv = masked[i]; bi = i; }
            masked[bi] = -1e30f;
            id[r] = bi;
            wsum += scores[tk][bi];
        }
        float inv = SCALE / wsum;
        for (int r = 0; r < TOPK; r++) {
            int p = atomicAdd(&g_cnt[id[r]], 1);
            g_ids[t * TOPK + r] = id[r];
            g_wts[t * TOPK + r] = scores[tk][id[r]] * inv;
            g_pos[t * TOPK + r] = p;
            s_ids[tk][r] = id[r];
            s_pos[tk][r] = p;
        }
    }
    __syncthreads();

    for (int slot = 0; slot < 4 * TOPK; slot++) {
        int tt = slot / TOPK, r = slot % TOPK;
        int p = s_pos[tt][r];
        if (p >= CAP) continue;
        int e = s_ids[tt][r];
        const float4* src = (const float4*)(x + (size_t)(t0 + tt) * HDIM);
        __half* dst = g_buf16 + ((size_t)e * CAP + p) * HDIM;
        float4 v = src[tid];
        __half2 a = __floats2half2_rn(v.x, v.y);
        __half2 b = __floats2half2_rn(v.z, v.w);
        uint2 u = make_uint2(*(uint32_t*)&a, *(uint32_t*)&b);
        *(uint2*)(dst + tid * 4) = u;
    }
}

__global__ void conv16_kernel(const float* __restrict__ in, __half* __restrict__ out, int n4) {
    int i = blockIdx.x * blockDim.x + threadIdx.x;
    if (i < n4) {
        float4 v = ((const float4*)in)[i];
        __half2 a = __floats2half2_rn(v.x, v.y);
        __half2 b = __floats2half2_rn(v.z, v.w);
        uint2 u = make_uint2(*(uint32_t*)&a, *(uint32_t*)&b);
        *(uint2*)(out + (size_t)i * 4) = u;
    }
}

static __device__ __forceinline__ uint2 f4h(float4 v) {
    __half2 a = __floats2half2_rn(v.x, v.y);
    __half2 b = __floats2half2_rn(v.z, v.w);
    return make_uint2(*(uint32_t*)&a, *(uint32_t*)&b);
}

// ---------------- Fused up-proj + SiLU*Mul: 3-stage A pipeline ----------------
__global__ __launch_bounds__(256, 2)
void gemm13_mma(const __half* __restrict__ A0, int lda, size_t sAe,
                const float* __restrict__ B0, int ldb, size_t sBe, int halfOff,
                __half* __restrict__ C0, int ldc, size_t sCe,
                int Kdim, const int* __restrict__ cnt)
{
    __shared__ __align__(16) __half As[3 * ABUF];
    __shared__ __align__(16) __half Bs[2 * BBUF];

    int e = blockIdx.z;
    int m0 = blockIdx.y * 128;
    if (cnt && m0 >= cnt[e]) return;
    int n0 = blockIdx.x * 64;

    int tid = threadIdx.x;
    int warp = tid >> 5, lane = tid & 31;
    int mw = warp & 1, nw = warp >> 1;

    const __half* A = A0 + (size_t)e * sAe + (size_t)m0 * lda;
    const float*  B = B0 + (size_t)e * sBe;
    uint32_t AsU = s2u(As), BsU = s2u(Bs);

    int ar = tid >> 1, acol = (tid & 1) * 16;
    int br = tid >> 3, sg = tid & 7;
    int bcolg = (sg < 4) ? (n0 + sg * 16) : (halfOff + n0 + (sg - 4) * 16);
    int bcols = (sg < 4) ? (sg * 16) : (64 + (sg - 4) * 16);
    const __half* Ag = A + (size_t)ar * lda + acol;
    const float*  Bg = B + (size_t)br * ldb + bcolg;

    float accg[4][2][4] = {}, accu[4][2][4] = {};
    float4 rbf[4];

    auto cpaA = [&](int b, int k0) {
        uint32_t d = AsU + (uint32_t)(b * ABUF + ar * LDA_S + acol) * 2;
        const __half* s = Ag + k0;
        CPA16(d, s);
        CPA16(d + 16, s + 8);
    };
    auto ldgB = [&](int k0) {
        const float4* bp = (const float4*)(Bg + (size_t)k0 * ldb);
        rbf[0] = bp[0]; rbf[1] = bp[1]; rbf[2] = bp[2]; rbf[3] = bp[3];
    };
    auto stsB = [&](int b) {
        uint2 h0 = f4h(rbf[0]), h1 = f4h(rbf[1]), h2 = f4h(rbf[2]), h3 = f4h(rbf[3]);
        uint4* bd = (uint4*)(Bs + b * BBUF + br * LDB_S + bcols);
        bd[0] = make_uint4(h0.x, h0.y, h1.x, h1.y);
        bd[1] = make_uint4(h2.x, h2.y, h3.x, h3.y);
    };

    int NC = Kdim / 32;
    ldgB(0);
    cpaA(0, 0); CP_COMMIT();
    cpaA(1, 32); CP_COMMIT();
    int bA = 0, bP = 2;
    for (int i = 0; i < NC; i++) {
        int bB = i & 1;
        stsB(bB);
        if (i + 1 < NC) ldgB((i + 1) * 32);
        if (i == NC - 1) CP_WAIT0(); else CP_WAIT1();   // A group i drained
        __syncthreads();
        if (i + 2 < NC) {
            cpaA(bP, (i + 2) * 32);   // writes buffer (i+2)%3; its readers (iter i-1) retired
            CP_COMMIT();
        }

        uint32_t ab = AsU + (uint32_t)(bA * ABUF) * 2;
        uint32_t bb = BsU + (uint32_t)(bB * BBUF) * 2;
        #pragma unroll
        for (int ks = 0; ks < 32; ks += 16) {
            uint32_t af[4][4];
            #pragma unroll
            for (int mi = 0; mi < 4; mi++) {
                int r = mw * 64 + mi * 16 + (lane & 15);
                LDSM4(af[mi], ab + (uint32_t)(r * LDA_S + ks + (lane >> 4) * 8) * 2);
            }
            uint32_t bgf[4], buf[4];
            int kr = ks + (lane & 15);
            LDSM4T(bgf, bb + (uint32_t)(kr * LDB_S + nw * 16 + (lane >> 4) * 8) * 2);
            LDSM4T(buf, bb + (uint32_t)(kr * LDB_S + 64 + nw * 16 + (lane >> 4) * 8) * 2);
            #pragma unroll
            for (int mi = 0; mi < 4; mi++) {
                MMA16816(accg[mi][0], af[mi], bgf[0], bgf[1]);
                MMA16816(accg[mi][1], af[mi], bgf[2], bgf[3]);
                MMA16816(accu[mi][0], af[mi], buf[0], buf[1]);
                MMA16816(accu[mi][1], af[mi], buf[2], buf[3]);
            }
        }
        bA = (bA == 2) ? 0 : bA + 1;
        bP = (bP == 2) ? 0 : bP + 1;
    }

    int g = lane >> 2, c = lane & 3;
    #pragma unroll
    for (int mi = 0; mi < 4; mi++) {
        #pragma unroll
        for (int j = 0; j < 2; j++) {
            float* G = accg[mi][j];
            float* U = accu[mi][j];
            int col = n0 + nw * 16 + j * 8 + 2 * c;
            int r0 = m0 + mw * 64 + mi * 16 + g;
            float s0 = G[0] / (1.f + expf(-G[0])) * U[0];
            float s1 = G[1] / (1.f + expf(-G[1])) * U[1];
            float s2 = G[2] / (1.f + expf(-G[2])) * U[2];
            float s3 = G[3] / (1.f + expf(-G[3])) * U[3];
            *(__half2*)(C0 + (size_t)e * sCe + (size_t)r0 * ldc + col) = __floats2half2_rn(s0, s1);
            *(__half2*)(C0 + (size_t)e * sCe + (size_t)(r0 + 8) * ldc + col) = __floats2half2_rn(s2, s3);
        }
    }
}

// ---------------- Plain GEMM: 3-stage A pipeline, templated out ----------------
template <typename OutT>
__global__ __launch_bounds__(256, 2)
void gemm2_mma(const __half* __restrict__ A0, int lda, size_t sAe,
               const float* __restrict__ B0, int ldb, size_t sBe,
               OutT* __restrict__ C0, int ldc, size_t sCe,
               int Kdim, const int* __restrict__ cnt)
{
    __shared__ __align__(16) __half As[3 * ABUF];
    __shared__ __align__(16) __half Bs[2 * BBUF];

    int e = blockIdx.z;
    int m0 = blockIdx.y * 128;
    if (cnt && m0 >= cnt[e]) return;
    int n0 = blockIdx.x * 128;

    int tid = threadIdx.x;
    int warp = tid >> 5, lane = tid & 31;
    int mw = warp & 1, nw = warp >> 1;

    const __half* A = A0 + (size_t)e * sAe + (size_t)m0 * lda;
    const float*  B = B0 + (size_t)e * sBe;
    uint32_t AsU = s2u(As), BsU = s2u(Bs);

    int ar = tid >> 1, acol = (tid & 1) * 16;
    int br = tid >> 3, sg = tid & 7;
    const __half* Ag = A + (size_t)ar * lda + acol;
    const float*  Bg = B + (size_t)br * ldb + n0 + sg * 16;

    float acc[4][4][4] = {};
    float4 rbf[4];

    auto cpaA = [&](int b, int k0) {
        uint32_t d = AsU + (uint32_t)(b * ABUF + ar * LDA_S + acol) * 2;
        const __half* s = Ag + k0;
        CPA16(d, s);
        CPA16(d + 16, s + 8);
    };
    auto ldgB = [&](int k0) {
        const float4* bp = (const float4*)(Bg + (size_t)k0 * ldb);
        rbf[0] = bp[0]; rbf[1] = bp[1]; rbf[2] = bp[2]; rbf[3] = bp[3];
    };
    auto stsB = [&](int b) {
        uint2 h0 = f4h(rbf[0]), h1 = f4h(rbf[1]), h2 = f4h(rbf[2]), h3 = f4h(rbf[3]);
        uint4* bd = (uint4*)(Bs + b * BBUF + br * LDB_S + sg * 16);
        bd[0] = make_uint4(h0.x, h0.y, h1.x, h1.y);
        bd[1] = make_uint4(h2.x, h2.y, h3.x, h3.y);
    };

    int NC = Kdim / 32;
    ldgB(0);
    cpaA(0, 0); CP_COMMIT();
    cpaA(1, 32); CP_COMMIT();
    int bA = 0, bP = 2;
    for (int i = 0; i < NC; i++) {
        int bB = i & 1;
        stsB(bB);
        if (i + 1 < NC) ldgB((i + 1) * 32);
        if (i == NC - 1) CP_WAIT0(); else CP_WAIT1();
        __syncthreads();
        if (i + 2 < NC) {
            cpaA(bP, (i + 2) * 32);
            CP_COMMIT();
        }

        uint32_t ab = AsU + (uint32_t)(bA * ABUF) * 2;
        uint32_t bb = BsU + (uint32_t)(bB * BBUF) * 2;
        #pragma unroll
        for (int ks = 0; ks < 32; ks += 16) {
            uint32_t af[4][4];
            #pragma unroll
            for (int mi = 0; mi < 4; mi++) {
                int r = mw * 64 + mi * 16 + (lane & 15);
                LDSM4(af[mi], ab + (uint32_t)(r * LDA_S + ks + (lane >> 4) * 8) * 2);
            }
            uint32_t bf0[4], bf1[4];
            int kr = ks + (lane & 15);
            LDSM4T(bf0, bb + (uint32_t)(kr * LDB_S + nw * 32 + (lane >> 4) * 8) * 2);
            LDSM4T(bf1, bb + (uint32_t)(kr * LDB_S + nw * 32 + 16 + (lane >> 4) * 8) * 2);
            #pragma unroll
            for (int mi = 0; mi < 4; mi++) {
                MMA16816(acc[mi][0], af[mi], bf0[0], bf0[1]);
                MMA16816(acc[mi][1], af[mi], bf0[2], bf0[3]);
                MMA16816(acc[mi][2], af[mi], bf1[0], bf1[1]);
                MMA16816(acc[mi][3], af[mi], bf1[2], bf1[3]);
            }
        }
        bA = (bA == 2) ? 0 : bA + 1;
        bP = (bP == 2) ? 0 : bP + 1;
    }

    int g = lane >> 2, c = lane & 3;
    #pragma unroll
    for (int mi = 0; mi < 4; mi++) {
        #pragma unroll
        for (int j = 0; j < 4; j++) {
            float* D = acc[mi][j];
            int col = n0 + nw * 32 + j * 8 + 2 * c;
            int r0 = m0 + mw * 64 + mi * 16 + g;
            OutT* Cb = C0 + (size_t)e * sCe;
            if constexpr (sizeof(OutT) == 4) {
                *(float2*)((float*)Cb + (size_t)r0 * ldc + col) = make_float2(D[0], D[1]);
                *(float2*)((float*)Cb + (size_t)(r0 + 8) * ldc + col) = make_float2(D[2], D[3]);
            } else {
                *(__half2*)((__half*)Cb + (size_t)r0 * ldc + col) = __floats2half2_rn(D[0], D[1]);
                *(__half2*)((__half*)Cb + (size_t)(r0 + 8) * ldc + col) = __floats2half2_rn(D[2], D[3]);
            }
        }
    }
}

// ---------------- Combine (eo fp16) ----------------
__global__ void combine_kernel(float* __restrict__ out) {
    int t = blockIdx.x;
    int h = threadIdx.x;
    int ids[TOPK], pos[TOPK]; float w[TOPK];
    #pragma unroll
    for (int k = 0; k < TOPK; k++) {
        ids[k] = g_ids[t * TOPK + k];
        pos[k] = g_pos[t * TOPK + k];
        w[k]   = g_wts[t * TOPK + k];
    }
    float4* o4 = (float4*)(out + (size_t)t * HDIM);
    float4 acc = o4[h];
    #pragma unroll
    for (int k = 0; k < TOPK; k++) {
        if (pos[k] < CAP) {
            const uint2* v2 = (const uint2*)(g_eo16 + ((size_t)ids[k] * CAP + pos[k]) * HDIM);
            uint2 u = v2[h];
            float2 fa = __half22float2(*(__half2*)&u.x);
            float2 fb = __half22float2(*(__half2*)&u.y);
            acc.x = fmaf(w[k], fa.x, acc.x);
            acc.y = fmaf(w[k], fa.y, acc.y);
            acc.z = fmaf(w[k], fb.x, acc.z);
            acc.w = fmaf(w[k], fb.y, acc.w);
        }
    }
    o4[h] = acc;
}

// ---------------- Launch ----------------
extern "C" void kernel_launch(void* const* d_in, const int* in_sizes, int n_in,
                              void* d_out, int out_size)
{
    const float* x      = (const float*)d_in[0];
    const float* gate_w = (const float*)d_in[1];
    const float* bias   = (const float*)d_in[2];
    const float* w13    = (const float*)d_in[3];
    const float* w2     = (const float*)d_in[4];
    const float* sw13   = (const float*)d_in[5];
    const float* sw2    = (const float*)d_in[6];
    float* out = (float*)d_out;

    __half *buf16, *act16, *eo16, *x16, *acts16;
    float* logP; int* cnt;
    cudaGetSymbolAddress((void**)&buf16,  g_buf16);
    cudaGetSymbolAddress((void**)&act16,  g_act16);
    cudaGetSymbolAddress((void**)&eo16,   g_eo16);
    cudaGetSymbolAddress((void**)&x16,    g_x16);
    cudaGetSymbolAddress((void**)&acts16, g_acts16);
    cudaGetSymbolAddress((void**)&logP,   g_logP);
    cudaGetSymbolAddress((void**)&cnt,    g_cnt);

    static cudaStream_t s2 = nullptr, s3 = nullptr;
    static cudaEvent_t evA = nullptr, evSh = nullptr, evTk = nullptr, evG2 = nullptr;
    if (!s2) {
        cudaStreamCreateWithFlags(&s2, cudaStreamNonBlocking);
        cudaStreamCreateWithFlags(&s3, cudaStreamNonBlocking);
        cudaEventCreateWithFlags(&evA,  cudaEventDisableTiming);
        cudaEventCreateWithFlags(&evSh, cudaEventDisableTiming);
        cudaEventCreateWithFlags(&evTk, cudaEventDisableTiming);
        cudaEventCreateWithFlags(&evG2, cudaEventDisableTiming);
    }

    const int EHALF = NEXP / 2;   // 32 experts per chain
    const size_t sAe = (size_t)CAP * HDIM;
    const size_t sBe13 = (size_t)HDIM * 2 * FDIM;
    const size_t sCe13 = (size_t)CAP * FDIM;
    const size_t sBe2 = (size_t)FDIM * HDIM;
    const size_t sCe2 = (size_t)CAP * HDIM;

    // fork point
    cudaEventRecord(evA, 0);
    cudaStreamWaitEvent(s2, evA, 0);

    // ---- main stream: routing, then expert chain [0,32) ----
    gate_logits_kernel<<<dim3(T_TOK / 16, KSPLIT), 256>>>(x, gate_w, logP);   // #1
    topk_kernel<<<T_TOK / 4, 256>>>(logP, bias, x);                           // #2
    cudaEventRecord(evTk, 0);
    cudaStreamWaitEvent(s3, evTk, 0);

    gemm13_mma<<<dim3(FDIM / 64, CAP / 128, EHALF), 256>>>(                   // #3
        buf16, HDIM, sAe, w13, 2 * FDIM, sBe13, FDIM,
        act16, FDIM, sCe13, HDIM, cnt);
    gemm2_mma<__half><<<dim3(HDIM / 128, CAP / 128, EHALF), 256>>>(           // #4 <- profile target
        act16, FDIM, sCe13, w2, HDIM, sBe2,
        eo16, HDIM, sCe2, FDIM, cnt);

    // ---- stream s3: expert chain [32,64) ----
    gemm13_mma<<<dim3(FDIM / 64, CAP / 128, EHALF), 256, 0, s3>>>(
        buf16 + EHALF * sAe, HDIM, sAe,
        w13 + EHALF * sBe13, 2 * FDIM, sBe13, FDIM,
        act16 + EHALF * sCe13, FDIM, sCe13, HDIM, cnt + EHALF);
    gemm2_mma<__half><<<dim3(HDIM / 128, CAP / 128, EHALF), 256, 0, s3>>>(
        act16 + EHALF * sCe13, FDIM, sCe13,
        w2 + EHALF * sBe2, HDIM, sBe2,
        eo16 + EHALF * sCe2, HDIM, sCe2, FDIM, cnt + EHALF);
    cudaEventRecord(evG2, s3);

    // ---- stream s2: shared-expert chain ----
    conv16_kernel<<<(T_TOK * HDIM / 4 + 255) / 256, 256, 0, s2>>>(x, x16, T_TOK * HDIM / 4);
    gemm13_mma<<<dim3(FSH / 64, T_TOK / 128, 1), 256, 0, s2>>>(
        x16, HDIM, 0, sw13, 2 * FSH, 0, FSH, acts16, FSH, 0, HDIM, nullptr);
    gemm2_mma<float><<<dim3(HDIM / 128, T_TOK / 128, 1), 256, 0, s2>>>(
        acts16, FSH, 0, sw2, HDIM, 0, out, HDIM, 0, FSH, nullptr);
    cudaEventRecord(evSh, s2);

    // join all branches, then combine
    cudaStreamWaitEvent(0, evG2, 0);
    cudaStreamWaitEvent(0, evSh, 0);
    combine_kernel<<<T_TOK, 256>>>(out);
}